// round 16
// baseline (speedup 1.0000x reference)
#include <cuda_runtime.h>
#include <cstdint>

// ---------------------------------------------------------------------------
// SelfAttention: out = softmax((xWq^T+bq)(xWk^T+bk)^T / sqrt(D)) (xWv^T+bv)
// B=4, S=2048, D=1024. fp32 I/O.
// Round 14: persistent work-queue kernel. ONE 444-CTA launch executes all
// 3584 GEMM tiles (QKV 1536 -> EXP 1024 -> PV 1024, all K=1024) from a global
// ticket counter; per-batch dependency counters let later phases backfill
// earlier phases' tail waves (streams are banned: creation allocates device
// memory). Operand loads are cp.async.cg (L2-only) so cross-CTA visibility
// needs only the threadfence/atomic release-acquire pattern. xr/wr moved to
// dedicated buffers (aliasing g_s would race under pipelining).
// Mainloop frozen at the R3 config; TF32 mma.sync, operands pre-rounded.
// ---------------------------------------------------------------------------

#define DEV_INLINE __device__ __forceinline__

static constexpr int Bsz = 4;
static constexpr int S   = 2048;
static constexpr int D   = 1024;
static constexpr int MQK = Bsz * S;
static constexpr int N2  = 2 * D;             // Q|K width (g_qk row stride)
static constexpr int N3  = 3 * D;             // fused QKV width

// Scratch (static __device__ arrays: allocation-free per harness rules)
__device__ float g_xr [(size_t)MQK * D];      // tf32-rounded x (32MB)
__device__ float g_wr [(size_t)3 * D * D];    // tf32-rounded Wq|Wk|Wv (12MB)
__device__ float g_qk [(size_t)MQK * N2];     // Q|K output (64MB)
__device__ float g_vT [(size_t)Bsz * D * S];  // V stored transposed (32MB)
__device__ float g_s  [(size_t)Bsz * S * S];  // E = exp(scores) (64MB)
__device__ float g_p  [(size_t)2 * Bsz * S * D]; // PV split-K partials (64MB)
__device__ float g_b  [N3];                   // concat bias bq|bk|bv
__device__ float g_inv[MQK];                  // 1 / rowsum(E)

// Work-queue state (reset by prep each call)
__device__ int g_work;
__device__ int g_done_qkv[Bsz];
__device__ int g_done_exp[Bsz];

static constexpr int QKV_TILES = Bsz * 384;   // 24 x 16 per batch
static constexpr int EXP_TILES = Bsz * 256;   // 16 x 16 per batch
static constexpr int PV_TILES  = Bsz * 256;   // 2 halves x (8 x 16)
static constexpr int QKV_END   = QKV_TILES;                // 1536
static constexpr int EXP_END   = QKV_END + EXP_TILES;      // 2560
static constexpr int TOTAL_TILES = EXP_END + PV_TILES;     // 3584

DEV_INLINE float tf32_round(float x) {
    uint32_t u;
    asm("cvt.rna.tf32.f32 %0, %1;" : "=r"(u) : "f"(x));
    return __uint_as_float(u);
}

DEV_INLINE uint32_t smem_u32(const void* p) {
    uint32_t a;
    asm("{ .reg .u64 t; cvta.to.shared.u64 t, %1; cvt.u32.u64 %0, t; }"
        : "=r"(a) : "l"(p));
    return a;
}

DEV_INLINE void cp_async16(uint32_t dst, const void* src) {
    asm volatile("cp.async.cg.shared.global [%0], [%1], 16;"
                 :: "r"(dst), "l"(src) : "memory");
}
DEV_INLINE void cp_commit() {
    asm volatile("cp.async.commit_group;" ::: "memory");
}
template <int N> DEV_INLINE void cp_wait() {
    asm volatile("cp.async.wait_group %0;" :: "n"(N) : "memory");
}

DEV_INLINE void mma_16x8x8(float acc[4], const uint32_t a[4], const uint32_t b[2]) {
    asm volatile(
        "mma.sync.aligned.m16n8k8.row.col.f32.tf32.tf32.f32 "
        "{%0,%1,%2,%3}, {%4,%5,%6,%7}, {%8,%9}, {%0,%1,%2,%3};\n"
        : "+f"(acc[0]), "+f"(acc[1]), "+f"(acc[2]), "+f"(acc[3])
        : "r"(a[0]), "r"(a[1]), "r"(a[2]), "r"(a[3]),
          "r"(b[0]), "r"(b[1]));
}

// ---------------------------------------------------------------------------
// prep_kernel: rounds x / weights, copies bias, resets work-queue counters.
// ---------------------------------------------------------------------------
static constexpr int PREP_XB = MQK * D / 4 / 256;        // 8192
static constexpr int PREP_WB = D * D / 4 / 256;          // 1024
static constexpr int PREP_BLOCKS = PREP_XB + 3 * PREP_WB + 4;

__global__ void __launch_bounds__(256)
prep_kernel(const float* __restrict__ x,
            const float* __restrict__ Wq, const float* __restrict__ Wk,
            const float* __restrict__ Wv,
            const float* __restrict__ bq, const float* __restrict__ bk,
            const float* __restrict__ bv,
            float* __restrict__ xr, float* __restrict__ wr,
            float* __restrict__ br)
{
    const int b = blockIdx.x;
    const int t = threadIdx.x;
    if (b < PREP_XB) {
        const int i = b * 256 + t;
        float4 v = reinterpret_cast<const float4*>(x)[i];
        v.x = tf32_round(v.x); v.y = tf32_round(v.y);
        v.z = tf32_round(v.z); v.w = tf32_round(v.w);
        reinterpret_cast<float4*>(xr)[i] = v;
    } else if (b < PREP_XB + 3 * PREP_WB) {
        const int wi = b - PREP_XB;
        const int w  = wi >> 10;                 // 0,1,2
        const int i  = (wi & 1023) * 256 + t;
        const float* src = (w == 0) ? Wq : (w == 1) ? Wk : Wv;
        float* dst = wr + (size_t)w * D * D;
        float4 v = reinterpret_cast<const float4*>(src)[i];
        v.x = tf32_round(v.x); v.y = tf32_round(v.y);
        v.z = tf32_round(v.z); v.w = tf32_round(v.w);
        reinterpret_cast<float4*>(dst)[i] = v;
    } else if (b < PREP_XB + 3 * PREP_WB + 3) {
        const int w = b - PREP_XB - 3 * PREP_WB; // 0,1,2
        const float* src = (w == 0) ? bq : (w == 1) ? bk : bv;
        reinterpret_cast<float4*>(br + w * D)[t] =
            reinterpret_cast<const float4*>(src)[t];
    } else {
        // reset work-queue counters
        if (t == 0) g_work = 0;
        if (t >= 1 && t < 1 + Bsz)        g_done_qkv[t - 1] = 0;
        if (t >= 1 + Bsz && t < 1 + 2*Bsz) g_done_exp[t - 1 - Bsz] = 0;
    }
}

// ---------------------------------------------------------------------------
// Persistent work-queue GEMM kernel. 444 CTAs, each loops over tiles.
// Tile body = frozen R3 mainloop (2-stage cp.async, two bars, 4 warps 64x64),
// K = 1024 for every tile. Per-tile runtime config decoded from tile index:
//   [0, 1536)    QKV: C=qk (cols<2048) or transposed V -> vT (cols>=2048)
//   [1536, 2560) EXP: E = exp(Q K^T / 32), depends on done_qkv[b]==384
//   [2560, 3584) PV halves: partials, depends on done_exp[b]==256
// ---------------------------------------------------------------------------
static constexpr int BM = 128, BN = 128, BK = 32;
static constexpr int KDIM  = 1024;               // every tile's K
static constexpr int NST   = KDIM / BK;          // 32 stages
static constexpr int ROWF  = BK + 4;             // 36 floats/row (16B-aligned)
static constexpr int STG   = BM * ROWF;          // floats per operand stage
static constexpr int DYN_SMEM = 4 * STG * 4;     // 2 stages x (A+B) = 73728 B
static constexpr int TPS = 132;                  // transpose stage row stride
static constexpr int GRID_PERSIST = 444;         // 3 CTAs/SM x 148 SMs

__global__ void __launch_bounds__(128, 3)
persist_kernel(const float* __restrict__ xr, const float* __restrict__ wr,
               const float* __restrict__ bconc,
               float* __restrict__ qk, float* __restrict__ vT,
               float* __restrict__ Em, float* __restrict__ pp)
{
    extern __shared__ float dyn[];
    float* As = dyn;                 // [2][STG]
    float* Bs = dyn + 2 * STG;       // [2][STG]
    const uint32_t sA = smem_u32(As);
    const uint32_t sB = smem_u32(Bs);
    __shared__ int s_idx;

    const int tid  = threadIdx.x;
    const int wid  = tid >> 5;
    const int lane = tid & 31;
    const int m_w  = (wid & 1) * 64;          // 2 warps along M
    const int n_w  = (wid >> 1) * 64;         // 2 warps along N
    const int group = lane >> 2;              // 0..7
    const int tig   = lane & 3;               // 0..3
    const int lr = tid >> 3;                  // loader base row 0..15
    const int lc = tid & 7;                   // loader float4 col 0..7

    for (;;) {
        if (tid == 0) s_idx = atomicAdd(&g_work, 1);
        __syncthreads();
        const int idx = s_idx;
        if (idx >= TOTAL_TILES) break;

        // ---- decode tile ----
        const float *A, *B;
        const float* bias = nullptr;
        float* C; float* vt = nullptr;
        int lda, ldb, ldc, bm, bn;
        float alpha = 1.0f;
        bool do_exp = false, do_round = true;
        int* dep = nullptr; int dep_t = 0;
        int* done = nullptr;

        if (idx < QKV_END) {
            const int b = idx / 384, t = idx % 384;
            bn = (t % 24) * BN; bm = (t / 24) * BM;
            A = xr + (size_t)b * S * D;  lda = D;
            B = wr;                      ldb = D;
            C = qk + (size_t)b * S * N2; ldc = N2;
            bias = bconc;
            vt = vT + (size_t)b * D * S;
            done = &g_done_qkv[b];
        } else if (idx < EXP_END) {
            const int e = idx - QKV_END, b = e / 256, t = e % 256;
            bn = (t % 16) * BN; bm = (t / 16) * BM;
            const float* q = qk + (size_t)b * S * N2;
            A = q;     lda = N2;
            B = q + D; ldb = N2;
            C = Em + (size_t)b * S * S; ldc = S;
            alpha = 0.03125f; do_exp = true;
            dep = &g_done_qkv[b]; dep_t = 384;
            done = &g_done_exp[b];
        } else {
            const int p = idx - EXP_END, b = p / 256, t = p % 256;
            const int h = t >> 7, q2 = t & 127;
            bn = (q2 % 8) * BN; bm = (q2 / 8) * BM;
            A = Em + (size_t)b * S * S + h * KDIM; lda = S;
            B = vT + (size_t)b * D * S + h * KDIM; ldb = S;
            C = pp + (size_t)(b * 2 + h) * S * D;  ldc = D;
            do_round = false;
            dep = &g_done_exp[b]; dep_t = 256;
        }

        // ---- dependency wait (acquire) ----
        if (dep) {
            if (tid == 0) {
                while (atomicAdd(dep, 0) < dep_t) __nanosleep(200);
                __threadfence();
            }
            __syncthreads();
        }

        // ---- tile body: frozen R3 mainloop ----
        float acc[4][8][4];
        #pragma unroll
        for (int mi = 0; mi < 4; mi++)
            #pragma unroll
            for (int ni = 0; ni < 8; ni++)
                #pragma unroll
                for (int r = 0; r < 4; r++) acc[mi][ni][r] = 0.0f;

        auto load_stage = [&](int s, int k0) {
            const uint32_t offA = sA + (uint32_t)s * STG * 4;
            const uint32_t offB = sB + (uint32_t)s * STG * 4;
            #pragma unroll
            for (int i = 0; i < 8; i++) {
                const int r = lr + 16 * i;
                cp_async16(offA + (uint32_t)(r * ROWF + lc * 4) * 4,
                           &A[(size_t)(bm + r) * lda + k0 + lc * 4]);
            }
            #pragma unroll
            for (int i = 0; i < 8; i++) {
                const int r = lr + 16 * i;
                cp_async16(offB + (uint32_t)(r * ROWF + lc * 4) * 4,
                           &B[(size_t)(bn + r) * ldb + k0 + lc * 4]);
            }
            cp_commit();
        };

        load_stage(0, 0);

        for (int i = 0; i < NST; i++) {
            if (i + 1 < NST) {
                load_stage((i + 1) & 1, (i + 1) * BK);
                cp_wait<1>();
            } else {
                cp_wait<0>();
            }
            __syncthreads();

            const float* as = As + (i & 1) * STG;
            const float* bs = Bs + (i & 1) * STG;

            #pragma unroll
            for (int ks = 0; ks < BK; ks += 8) {
                uint32_t afr[4][4];
                #pragma unroll
                for (int mi = 0; mi < 4; mi++) {
                    const int r = m_w + mi * 16;
                    afr[mi][0] = __float_as_uint(as[(r + group    ) * ROWF + ks + tig    ]);
                    afr[mi][1] = __float_as_uint(as[(r + group + 8) * ROWF + ks + tig    ]);
                    afr[mi][2] = __float_as_uint(as[(r + group    ) * ROWF + ks + tig + 4]);
                    afr[mi][3] = __float_as_uint(as[(r + group + 8) * ROWF + ks + tig + 4]);
                }
                uint32_t bfr[8][2];
                #pragma unroll
                for (int ni = 0; ni < 8; ni++) {
                    const int c = n_w + ni * 8;
                    bfr[ni][0] = __float_as_uint(bs[(c + group) * ROWF + ks + tig    ]);
                    bfr[ni][1] = __float_as_uint(bs[(c + group) * ROWF + ks + tig + 4]);
                }
                #pragma unroll
                for (int mi = 0; mi < 4; mi++)
                    #pragma unroll
                    for (int ni = 0; ni < 8; ni++)
                        mma_16x8x8(acc[mi][ni], afr[mi], bfr[ni]);
            }
            __syncthreads();
        }

        // ---- epilogue (runtime flags) ----
        const bool v_block = (vt != nullptr) && (bn >= N2);

        #pragma unroll
        for (int mi = 0; mi < 4; mi++) {
            const int rloc0 = m_w + mi * 16 + group;
            const int row0  = bm + rloc0;
            #pragma unroll
            for (int ni = 0; ni < 8; ni++) {
                const int cloc0 = n_w + ni * 8 + tig * 2;
                const int col0  = bn + cloc0;
                float v00 = acc[mi][ni][0] * alpha;
                float v01 = acc[mi][ni][1] * alpha;
                float v10 = acc[mi][ni][2] * alpha;
                float v11 = acc[mi][ni][3] * alpha;
                if (bias) {
                    const float b0 = bias[col0], b1 = bias[col0 + 1];
                    v00 += b0; v01 += b1; v10 += b0; v11 += b1;
                }
                if (do_exp) {
                    v00 = __expf(v00); v01 = __expf(v01);
                    v10 = __expf(v10); v11 = __expf(v11);
                }
                if (do_round) {
                    v00 = tf32_round(v00); v01 = tf32_round(v01);
                    v10 = tf32_round(v10); v11 = tf32_round(v11);
                }
                if (!v_block) {
                    *reinterpret_cast<float2*>(&C[(size_t)row0 * ldc + col0]) =
                        make_float2(v00, v01);
                    *reinterpret_cast<float2*>(&C[(size_t)(row0 + 8) * ldc + col0]) =
                        make_float2(v10, v11);
                } else {
                    dyn[(size_t)cloc0 * TPS + rloc0]           = v00;
                    dyn[(size_t)(cloc0 + 1) * TPS + rloc0]     = v01;
                    dyn[(size_t)cloc0 * TPS + rloc0 + 8]       = v10;
                    dyn[(size_t)(cloc0 + 1) * TPS + rloc0 + 8] = v11;
                }
            }
        }

        if (v_block) {
            __syncthreads();
            const int d0 = bn - N2;                // head-dim offset
            #pragma unroll
            for (int j = 0; j < 32; j++) {
                const int dr = wid * 32 + j;
                const float4 v = *reinterpret_cast<const float4*>(
                    &dyn[(size_t)dr * TPS + lane * 4]);
                *reinterpret_cast<float4*>(
                    &vt[(size_t)(d0 + dr) * S + bm + lane * 4]) = v;
            }
        }

        // ---- completion (release) ----
        __threadfence();
        __syncthreads();
        if (tid == 0 && done) atomicAdd(done, 1);
    }
}

// ---------------------------------------------------------------------------
// inv-rowsum reduction: g_inv[row] = 1 / sum(E[row, :]); rows batch-major.
// ---------------------------------------------------------------------------
__global__ void __launch_bounds__(256)
rowsum_inv_kernel(const float* __restrict__ E, float* __restrict__ inv, int ncols)
{
    const float4* p = reinterpret_cast<const float4*>(E + (size_t)blockIdx.x * ncols);
    const int tid  = threadIdx.x;
    const int warp = tid >> 5;
    const int lane = tid & 31;

    __shared__ float red[8];

    float sum = 0.f;
    #pragma unroll
    for (int i = 0; i < 2; i++) {
        const float4 v = p[tid + 256 * i];
        sum += (v.x + v.y) + (v.z + v.w);
    }
    #pragma unroll
    for (int o = 16; o > 0; o >>= 1)
        sum += __shfl_xor_sync(0xffffffffu, sum, o);
    if (lane == 0) red[warp] = sum;
    __syncthreads();
    if (tid == 0) {
        float total = 0.f;
        #pragma unroll
        for (int w = 0; w < 8; w++) total += red[w];
        inv[blockIdx.x] = 1.0f / total;
    }
}

// ---------------------------------------------------------------------------
// combine: out[r][:] = (p[2b][sr][:] + p[2b+1][sr][:]) * inv[r]
// ---------------------------------------------------------------------------
__global__ void __launch_bounds__(256)
combine_kernel(const float* __restrict__ p, const float* __restrict__ inv,
               float* __restrict__ out)
{
    const int r  = blockIdx.x;          // 0..8191
    const int t  = threadIdx.x;
    const int b  = r >> 11;             // batch (2048 rows each)
    const int sr = r & 2047;
    const float4* a0 = reinterpret_cast<const float4*>(
        p + ((size_t)(2 * b)     * S + sr) * D);
    const float4* a1 = reinterpret_cast<const float4*>(
        p + ((size_t)(2 * b + 1) * S + sr) * D);
    const float s = inv[r];
    const float4 u = a0[t];
    const float4 v = a1[t];
    float4 o;
    o.x = (u.x + v.x) * s;  o.y = (u.y + v.y) * s;
    o.z = (u.z + v.z) * s;  o.w = (u.w + v.w) * s;
    reinterpret_cast<float4*>(out + (size_t)r * D)[t] = o;
}

// ---------------------------------------------------------------------------
extern "C" void kernel_launch(void* const* d_in, const int* in_sizes, int n_in,
                              void* d_out, int out_size)
{
    const float* x  = (const float*)d_in[0];
    const float* Wq = (const float*)d_in[1];
    const float* bq = (const float*)d_in[2];
    const float* Wk = (const float*)d_in[3];
    const float* bk = (const float*)d_in[4];
    const float* Wv = (const float*)d_in[5];
    const float* bv = (const float*)d_in[6];
    float* out = (float*)d_out;

    float *gxr, *gwr, *gqk, *gvT, *gs, *gp, *gb, *ginv;
    cudaGetSymbolAddress((void**)&gxr,  g_xr);
    cudaGetSymbolAddress((void**)&gwr,  g_wr);
    cudaGetSymbolAddress((void**)&gqk,  g_qk);
    cudaGetSymbolAddress((void**)&gvT,  g_vT);
    cudaGetSymbolAddress((void**)&gs,   g_s);
    cudaGetSymbolAddress((void**)&gp,   g_p);
    cudaGetSymbolAddress((void**)&gb,   g_b);
    cudaGetSymbolAddress((void**)&ginv, g_inv);

    cudaFuncSetAttribute(persist_kernel,
                         cudaFuncAttributeMaxDynamicSharedMemorySize, DYN_SMEM);

    // 0) prep: round x + weights, concat bias, reset queue counters.
    prep_kernel<<<PREP_BLOCKS, 256>>>(x, Wq, Wk, Wv, bq, bk, bv, gxr, gwr, gb);

    // 1) persistent work queue: QKV -> EXP -> PV, pipelined across batches.
    persist_kernel<<<GRID_PERSIST, 128, DYN_SMEM>>>(gxr, gwr, gb,
                                                    gqk, gvT, gs, gp);

    // 2) inv rowsum of E (all batches; rows batch-major in g_s)
    rowsum_inv_kernel<<<MQK, 256>>>(gs, ginv, S);

    // 3) combine PV halves + softmax normalization
    combine_kernel<<<MQK, 256>>>(gp, ginv, out);
}